// round 1
// baseline (speedup 1.0000x reference)
#include <cuda_runtime.h>
#include <cstdint>

#define NN 50000
#define NE 400000
#define ET (NN + NE)
#define NEG_SLOPE 0.2f

// ---------------- scratch (device globals: the sanctioned no-alloc path) ----
__device__ float    g_xl[NN * 256];
__device__ float    g_xr[NN * 256];
__device__ float    g_hA[NN * 256];
__device__ float    g_hB[NN * 256];
__device__ float    g_p[ET * 2];        // logits, then exp(logit - max)
__device__ unsigned g_nmax[NN * 2];     // order-encoded float max
__device__ float    g_denom[NN * 2];
__device__ int      g_is64;

// ---------------- helpers ----------------------------------------------------
__device__ __forceinline__ unsigned fenc(float f) {
    unsigned u = __float_as_uint(f);
    return (u & 0x80000000u) ? ~u : (u | 0x80000000u);
}
__device__ __forceinline__ float fdec(unsigned u) {
    u = (u & 0x80000000u) ? (u ^ 0x80000000u) : ~u;
    return __uint_as_float(u);
}

__device__ __forceinline__ const float* selIn(const float* ext, int sel) {
    return sel == 1 ? g_hA : (sel == 2 ? g_hB : ext);
}
__device__ __forceinline__ float* selOut(float* ext, int sel) {
    return sel == 1 ? g_hA : (sel == 2 ? g_hB : ext);
}

// edge_index may be int32 (JAX x64 off) or int64 (x64 on). Detect once.
__global__ void detect64_kernel(const int* __restrict__ ei) {
    if (threadIdx.x == 0 && blockIdx.x == 0) {
        int all0 = 1;
        for (int i = 0; i < 64; i++)
            if (ei[2 * i + 1] != 0) all0 = 0;
        g_is64 = all0;
    }
}

__device__ __forceinline__ void load_edge(const void* ei, int e, int& s, int& d) {
    if (e >= NE) { s = d = e - NE; return; }   // self loops appended at the end
    if (g_is64) {
        const long long* p = (const long long*)ei;
        s = (int)p[e]; d = (int)p[NE + e];
    } else {
        const int* p = (const int*)ei;
        s = p[e]; d = p[NE + e];
    }
}

// ---------------- fp32 SIMT GEMM: C[M,N] = A[M,K] @ B[K,N] ------------------
// 128x128 block, 256 threads, 8x8 per thread, K-step 8. K,N multiples of 4/8.
__global__ __launch_bounds__(256, 2) void sgemm128(
    const float* __restrict__ Aext, int asel, int osel,
    const float* __restrict__ B, int M, int N, int K)
{
    __shared__ float As[8][128];
    __shared__ float Bs[8][128];

    const float* A = selIn(Aext, asel);
    float* C = (osel == 0) ? g_xl : g_xr;

    int tid = threadIdx.x;
    int tx = tid & 15, ty = tid >> 4;
    int rowBase = blockIdx.y * 128;
    int colBase = blockIdx.x * 128;

    int arow = tid >> 1, acol = (tid & 1) * 4;   // A tile 128x8
    int brow = tid >> 5, bcol = (tid & 31) * 4;  // B tile 8x128

    float acc[8][8];
#pragma unroll
    for (int i = 0; i < 8; i++)
#pragma unroll
        for (int j = 0; j < 8; j++) acc[i][j] = 0.f;

    for (int k0 = 0; k0 < K; k0 += 8) {
        float4 av = make_float4(0.f, 0.f, 0.f, 0.f);
        int gr = rowBase + arow;
        if (gr < M) av = *(const float4*)(A + (size_t)gr * K + k0 + acol);
        As[acol + 0][arow] = av.x;
        As[acol + 1][arow] = av.y;
        As[acol + 2][arow] = av.z;
        As[acol + 3][arow] = av.w;

        float4 bv = make_float4(0.f, 0.f, 0.f, 0.f);
        int gc = colBase + bcol;
        if (gc + 3 < N) bv = *(const float4*)(B + (size_t)(k0 + brow) * N + gc);
        *(float4*)&Bs[brow][bcol] = bv;

        __syncthreads();
#pragma unroll
        for (int k = 0; k < 8; k++) {
            float a[8], b[8];
#pragma unroll
            for (int i = 0; i < 8; i++) a[i] = As[k][ty * 8 + i];
#pragma unroll
            for (int j = 0; j < 8; j++) b[j] = Bs[k][tx * 8 + j];
#pragma unroll
            for (int i = 0; i < 8; i++)
#pragma unroll
                for (int j = 0; j < 8; j++) acc[i][j] += a[i] * b[j];
        }
        __syncthreads();
    }

#pragma unroll
    for (int i = 0; i < 8; i++) {
        int gr = rowBase + ty * 8 + i;
        if (gr >= M) continue;
#pragma unroll
        for (int j = 0; j < 8; j += 4) {
            int gc = colBase + tx * 8 + j;
            if (gc + 3 < N) {
                *(float4*)(C + (size_t)gr * N + gc) =
                    make_float4(acc[i][j], acc[i][j + 1], acc[i][j + 2], acc[i][j + 3]);
            }
        }
    }
}

// ---------------- edge kernels ----------------------------------------------
__global__ void init_md_kernel(int NH) {
    int i = blockIdx.x * blockDim.x + threadIdx.x;
    if (i < NH) { g_nmax[i] = 0x007FFFFFu; g_denom[i] = 0.f; }  // enc(-inf)
}

// warp per edge: logit[e,h] = att[h] . leaky_relu(xl[src,h] + xr[dst,h]); atomicMax into nmax[dst,h]
__global__ void edge_logits_kernel(const void* ei, const float* __restrict__ att,
                                   int H, int C)
{
    int warp = (blockIdx.x * blockDim.x + threadIdx.x) >> 5;
    int lane = threadIdx.x & 31;
    if (warp >= ET) return;
    int s, d; load_edge(ei, warp, s, d);
    int HC = H * C;
    const float* xls = g_xl + (size_t)s * HC;
    const float* xrd = g_xr + (size_t)d * HC;
    for (int h = 0; h < H; h++) {
        float acc = 0.f;
        for (int c = lane; c < C; c += 32) {
            float v = xls[h * C + c] + xrd[h * C + c];
            v = (v > 0.f) ? v : NEG_SLOPE * v;
            acc += v * att[h * C + c];
        }
#pragma unroll
        for (int o = 16; o; o >>= 1) acc += __shfl_xor_sync(0xffffffffu, acc, o);
        if (lane == 0) {
            g_p[(size_t)warp * H + h] = acc;
            atomicMax(&g_nmax[d * H + h], fenc(acc));
        }
    }
}

// thread per (edge, head): p = exp(logit - max[dst]); denom[dst] += p
__global__ void edge_exp_kernel(const void* ei, int H) {
    int i = blockIdx.x * blockDim.x + threadIdx.x;
    if (i >= ET * H) return;
    int e = i / H, h = i - e * H;
    int s, d; load_edge(ei, e, s, d);
    (void)s;
    float m = fdec(g_nmax[d * H + h]);
    float v = __expf(g_p[i] - m);
    g_p[i] = v;
    atomicAdd(&g_denom[d * H + h], v);
}

__global__ void init_out_kernel(float* outext, int osel,
                                const float* __restrict__ bias, int HC) {
    int i = blockIdx.x * blockDim.x + threadIdx.x;
    if (i >= NN * HC) return;
    selOut(outext, osel)[i] = bias[i % HC];
}

// warp per edge: out[dst] += alpha * xl[src] (vectorized global reduction)
__global__ void edge_scatter_kernel(const void* ei, float* outext, int osel,
                                    int H, int C)
{
    int warp = (blockIdx.x * blockDim.x + threadIdx.x) >> 5;
    int lane = threadIdx.x & 31;
    if (warp >= ET) return;
    int s, d; load_edge(ei, warp, s, d);
    int HC = H * C;
    const float* xls = g_xl + (size_t)s * HC;
    float* outd = selOut(outext, osel) + (size_t)d * HC;
    for (int h = 0; h < H; h++) {
        float alpha = g_p[(size_t)warp * H + h] / g_denom[d * H + h];
        for (int c = lane * 4; c < C; c += 128) {
            float4 v = *(const float4*)(xls + h * C + c);
            float* dst = outd + h * C + c;
            asm volatile("red.global.add.v4.f32 [%0], {%1,%2,%3,%4};"
                         :: "l"(dst),
                            "f"(alpha * v.x), "f"(alpha * v.y),
                            "f"(alpha * v.z), "f"(alpha * v.w)
                         : "memory");
        }
    }
}

// ---------------- launch -----------------------------------------------------
extern "C" void kernel_launch(void* const* d_in, const int* in_sizes, int n_in,
                              void* d_out, int out_size)
{
    const float* x  = (const float*)d_in[0];
    const void*  ei = d_in[1];
    const float* Wl[4]   = {(const float*)d_in[2],  (const float*)d_in[6],
                            (const float*)d_in[10], (const float*)d_in[14]};
    const float* Wr[4]   = {(const float*)d_in[3],  (const float*)d_in[7],
                            (const float*)d_in[11], (const float*)d_in[15]};
    const float* att[4]  = {(const float*)d_in[4],  (const float*)d_in[8],
                            (const float*)d_in[12], (const float*)d_in[16]};
    const float* bias[4] = {(const float*)d_in[5],  (const float*)d_in[9],
                            (const float*)d_in[13], (const float*)d_in[17]};
    float* out = (float*)d_out;

    detect64_kernel<<<1, 32>>>((const int*)ei);

    // layer: K, H, C, input selector (0=x ext, 1=hA, 2=hB), output selector
    const int cfgK[4] = {1024, 256, 256, 256};
    const int cfgH[4] = {2, 2, 2, 1};
    const int cfgC[4] = {128, 128, 128, 32};
    const int inSel[4]  = {0, 1, 2, 1};
    const int outSel[4] = {1, 2, 1, 0};

    for (int l = 0; l < 4; l++) {
        int K = cfgK[l], H = cfgH[l], C = cfgC[l], HC = H * C;

        dim3 gg((HC + 127) / 128, (NN + 127) / 128);
        sgemm128<<<gg, 256>>>(x, inSel[l], 0, Wl[l], NN, HC, K);
        sgemm128<<<gg, 256>>>(x, inSel[l], 1, Wr[l], NN, HC, K);

        init_md_kernel<<<(NN * H + 255) / 256, 256>>>(NN * H);

        edge_logits_kernel<<<(ET * 32 + 255) / 256, 256>>>(ei, att[l], H, C);
        edge_exp_kernel<<<(ET * H + 255) / 256, 256>>>(ei, H);

        init_out_kernel<<<(NN * HC + 255) / 256, 256>>>(out, outSel[l], bias[l], HC);
        edge_scatter_kernel<<<(ET * 32 + 255) / 256, 256>>>(ei, out, outSel[l], H, C);
    }
}

// round 2
// speedup vs baseline: 1.6325x; 1.6325x over previous
#include <cuda_runtime.h>
#include <cstdint>

#define NN 50000
#define NE 400000
#define ET (NN + NE)
#define NEG_SLOPE 0.2f

// ---------------- scratch (device globals: the sanctioned no-alloc path) ----
__device__ float    g_xl[NN * 256];
__device__ float    g_xr[NN * 256];
__device__ float    g_hA[NN * 256];
__device__ float    g_hB[NN * 256];
__device__ float    g_p[ET * 2];        // logits, then exp(logit - max)
__device__ unsigned g_nmax[NN * 2];     // order-encoded float max
__device__ float    g_denom[NN * 2];
__device__ int      g_is64;

// ---------------- helpers ----------------------------------------------------
__device__ __forceinline__ unsigned fenc(float f) {
    unsigned u = __float_as_uint(f);
    return (u & 0x80000000u) ? ~u : (u | 0x80000000u);
}
__device__ __forceinline__ float fdec(unsigned u) {
    u = (u & 0x80000000u) ? (u ^ 0x80000000u) : ~u;
    return __uint_as_float(u);
}

__device__ __forceinline__ const float* selIn(const float* ext, int sel) {
    return sel == 1 ? g_hA : (sel == 2 ? g_hB : ext);
}
__device__ __forceinline__ float* selOut(float* ext, int sel) {
    return sel == 1 ? g_hA : (sel == 2 ? g_hB : ext);
}

// round f32 -> tf32 (rna) once, at smem-store time
__device__ __forceinline__ float f2tf32(float f) {
    unsigned u;
    asm("cvt.rna.tf32.f32 %0, %1;" : "=r"(u) : "f"(f));
    return __uint_as_float(u);
}

// edge_index may be int32 (JAX x64 off) or int64 (x64 on). Detect once.
__global__ void detect64_kernel(const int* __restrict__ ei) {
    if (threadIdx.x == 0 && blockIdx.x == 0) {
        int all0 = 1;
        for (int i = 0; i < 64; i++)
            if (ei[2 * i + 1] != 0) all0 = 0;
        g_is64 = all0;
    }
}

__device__ __forceinline__ void load_edge(const void* ei, int e, int& s, int& d) {
    if (e >= NE) { s = d = e - NE; return; }   // self loops appended at the end
    if (g_is64) {
        const long long* p = (const long long*)ei;
        s = (int)p[e]; d = (int)p[NE + e];
    } else {
        const int* p = (const int*)ei;
        s = p[e]; d = p[NE + e];
    }
}

// ---------------- tf32 tensor-core GEMM --------------------------------------
// Computes [xl | xr] = A[M,K] @ [Wl | Wr]   (fusedN = 2*HC)
// Block tile 128x128x32, 256 threads = 8 warps (2m x 4n), warp tile 64x32,
// per-warp 4x4 grid of m16n8k8 tf32 MMAs.
#define MMA_TF32(d, a, b)                                                      \
    asm volatile(                                                              \
        "mma.sync.aligned.m16n8k8.row.col.f32.tf32.tf32.f32 "                  \
        "{%0,%1,%2,%3}, {%4,%5,%6,%7}, {%8,%9}, {%0,%1,%2,%3};"                \
        : "+f"(d[0]), "+f"(d[1]), "+f"(d[2]), "+f"(d[3])                       \
        : "r"(a[0]), "r"(a[1]), "r"(a[2]), "r"(a[3]), "r"(b[0]), "r"(b[1]))

__global__ __launch_bounds__(256, 2) void gemm_tf32(
    const float* __restrict__ Aext, int asel,
    const float* __restrict__ Wl, const float* __restrict__ Wr,
    int M, int HC, int fusedN, int K)
{
    __shared__ float As[128][36];   // stride 36: frag loads conflict-free
    __shared__ float Bs[32][132];   // stride 132: frag loads conflict-free

    const float* A = selIn(Aext, asel);

    int tid = threadIdx.x;
    int lane = tid & 31, warp = tid >> 5;
    int wm = (warp & 1) * 64, wn = (warp >> 1) * 32;
    int rowBase = blockIdx.y * 128, colBase = blockIdx.x * 128;

    float acc[4][4][4];
#pragma unroll
    for (int i = 0; i < 4; i++)
#pragma unroll
        for (int j = 0; j < 4; j++)
#pragma unroll
            for (int q = 0; q < 4; q++) acc[i][j][q] = 0.f;

    int aRow = tid >> 1, aCol = (tid & 1) * 16;    // A: 128 rows x 32 k
    int bRow = tid >> 3, bCol = (tid & 7) * 4;     // B: 32 k x 128 cols

    for (int k0 = 0; k0 < K; k0 += 32) {
        // ---- global -> shared: A tile (convert to tf32 on store)
        {
            int gr = rowBase + aRow;
            const float* ap = A + (size_t)gr * K + k0 + aCol;
#pragma unroll
            for (int j = 0; j < 4; j++) {
                float4 v = make_float4(0.f, 0.f, 0.f, 0.f);
                if (gr < M) v = *(const float4*)(ap + j * 4);
                int kc = aCol + j * 4;
                As[aRow][kc + 0] = f2tf32(v.x);
                As[aRow][kc + 1] = f2tf32(v.y);
                As[aRow][kc + 2] = f2tf32(v.z);
                As[aRow][kc + 3] = f2tf32(v.w);
            }
        }
        // ---- global -> shared: B tile ([Wl | Wr] fused along N)
        {
            int gk = k0 + bRow;
#pragma unroll
            for (int i = 0; i < 4; i++) {
                int col = bCol + i * 32;
                int gc = colBase + col;
                float4 v = make_float4(0.f, 0.f, 0.f, 0.f);
                if (gc < fusedN) {
                    const float* bp = (gc < HC)
                        ? (Wl + (size_t)gk * HC + gc)
                        : (Wr + (size_t)gk * HC + (gc - HC));
                    v = *(const float4*)bp;
                }
                Bs[bRow][col + 0] = f2tf32(v.x);
                Bs[bRow][col + 1] = f2tf32(v.y);
                Bs[bRow][col + 2] = f2tf32(v.z);
                Bs[bRow][col + 3] = f2tf32(v.w);
            }
        }
        __syncthreads();

        int r = lane >> 2, c = lane & 3;
#pragma unroll
        for (int ks = 0; ks < 4; ks++) {
            int kk = ks * 8;
            unsigned a[4][4], b[4][2];
#pragma unroll
            for (int mi = 0; mi < 4; mi++) {
                int rb = wm + mi * 16 + r;
                a[mi][0] = __float_as_uint(As[rb][kk + c]);
                a[mi][1] = __float_as_uint(As[rb + 8][kk + c]);
                a[mi][2] = __float_as_uint(As[rb][kk + c + 4]);
                a[mi][3] = __float_as_uint(As[rb + 8][kk + c + 4]);
            }
#pragma unroll
            for (int ni = 0; ni < 4; ni++) {
                int nb = wn + ni * 8 + r;
                b[ni][0] = __float_as_uint(Bs[kk + c][nb]);
                b[ni][1] = __float_as_uint(Bs[kk + c + 4][nb]);
            }
#pragma unroll
            for (int mi = 0; mi < 4; mi++)
#pragma unroll
                for (int ni = 0; ni < 4; ni++)
                    MMA_TF32(acc[mi][ni], a[mi], b[ni]);
        }
        __syncthreads();
    }

    // ---- epilogue: route columns to g_xl / g_xr
    int r = lane >> 2, c = (lane & 3) * 2;
#pragma unroll
    for (int mi = 0; mi < 4; mi++) {
#pragma unroll
        for (int ni = 0; ni < 4; ni++) {
            int col = colBase + wn + ni * 8 + c;
            if (col >= fusedN) continue;
            float* base; int cc;
            if (col < HC) { base = g_xl; cc = col; }
            else          { base = g_xr; cc = col - HC; }
#pragma unroll
            for (int half = 0; half < 2; half++) {
                int row = rowBase + wm + mi * 16 + r + half * 8;
                if (row < M) {
                    *(float2*)(base + (size_t)row * HC + cc) =
                        make_float2(acc[mi][ni][half * 2],
                                    acc[mi][ni][half * 2 + 1]);
                }
            }
        }
    }
}

// ---------------- edge kernels ----------------------------------------------
__global__ void init_md_kernel(int NH) {
    int i = blockIdx.x * blockDim.x + threadIdx.x;
    if (i < NH) { g_nmax[i] = 0x007FFFFFu; g_denom[i] = 0.f; }  // enc(-inf)
}

// warp per edge: logit[e,h] = att[h] . leaky_relu(xl[src,h] + xr[dst,h])
__global__ void edge_logits_kernel(const void* ei, const float* __restrict__ att,
                                   int H, int C)
{
    int warp = (blockIdx.x * blockDim.x + threadIdx.x) >> 5;
    int lane = threadIdx.x & 31;
    if (warp >= ET) return;
    int s, d; load_edge(ei, warp, s, d);
    int HC = H * C;
    const float* xls = g_xl + (size_t)s * HC;
    const float* xrd = g_xr + (size_t)d * HC;
    for (int h = 0; h < H; h++) {
        float acc = 0.f;
        for (int c = lane; c < C; c += 32) {
            float v = xls[h * C + c] + xrd[h * C + c];
            v = (v > 0.f) ? v : NEG_SLOPE * v;
            acc += v * att[h * C + c];
        }
#pragma unroll
        for (int o = 16; o; o >>= 1) acc += __shfl_xor_sync(0xffffffffu, acc, o);
        if (lane == 0) {
            g_p[(size_t)warp * H + h] = acc;
            atomicMax(&g_nmax[d * H + h], fenc(acc));
        }
    }
}

// thread per (edge, head): p = exp(logit - max[dst]); denom[dst] += p
__global__ void edge_exp_kernel(const void* ei, int H) {
    int i = blockIdx.x * blockDim.x + threadIdx.x;
    if (i >= ET * H) return;
    int e = i / H, h = i - e * H;
    int s, d; load_edge(ei, e, s, d);
    (void)s;
    float m = fdec(g_nmax[d * H + h]);
    float v = __expf(g_p[i] - m);
    g_p[i] = v;
    atomicAdd(&g_denom[d * H + h], v);
}

__global__ void init_out_kernel(float* outext, int osel,
                                const float* __restrict__ bias, int HC) {
    int i = blockIdx.x * blockDim.x + threadIdx.x;
    if (i >= NN * HC) return;
    selOut(outext, osel)[i] = bias[i % HC];
}

// warp per edge: out[dst] += alpha * xl[src] (vectorized global reduction)
__global__ void edge_scatter_kernel(const void* ei, float* outext, int osel,
                                    int H, int C)
{
    int warp = (blockIdx.x * blockDim.x + threadIdx.x) >> 5;
    int lane = threadIdx.x & 31;
    if (warp >= ET) return;
    int s, d; load_edge(ei, warp, s, d);
    int HC = H * C;
    const float* xls = g_xl + (size_t)s * HC;
    float* outd = selOut(outext, osel) + (size_t)d * HC;
    for (int h = 0; h < H; h++) {
        float alpha = g_p[(size_t)warp * H + h] / g_denom[d * H + h];
        for (int c = lane * 4; c < C; c += 128) {
            float4 v = *(const float4*)(xls + h * C + c);
            float* dst = outd + h * C + c;
            asm volatile("red.global.add.v4.f32 [%0], {%1,%2,%3,%4};"
                         :: "l"(dst),
                            "f"(alpha * v.x), "f"(alpha * v.y),
                            "f"(alpha * v.z), "f"(alpha * v.w)
                         : "memory");
        }
    }
}

// ---------------- launch -----------------------------------------------------
extern "C" void kernel_launch(void* const* d_in, const int* in_sizes, int n_in,
                              void* d_out, int out_size)
{
    const float* x  = (const float*)d_in[0];
    const void*  ei = d_in[1];
    const float* Wl[4]   = {(const float*)d_in[2],  (const float*)d_in[6],
                            (const float*)d_in[10], (const float*)d_in[14]};
    const float* Wr[4]   = {(const float*)d_in[3],  (const float*)d_in[7],
                            (const float*)d_in[11], (const float*)d_in[15]};
    const float* att[4]  = {(const float*)d_in[4],  (const float*)d_in[8],
                            (const float*)d_in[12], (const float*)d_in[16]};
    const float* bias[4] = {(const float*)d_in[5],  (const float*)d_in[9],
                            (const float*)d_in[13], (const float*)d_in[17]};
    float* out = (float*)d_out;

    detect64_kernel<<<1, 32>>>((const int*)ei);

    // layer: K, H, C, input selector (0=x ext, 1=hA, 2=hB), output selector
    const int cfgK[4] = {1024, 256, 256, 256};
    const int cfgH[4] = {2, 2, 2, 1};
    const int cfgC[4] = {128, 128, 128, 32};
    const int inSel[4]  = {0, 1, 2, 1};
    const int outSel[4] = {1, 2, 1, 0};

    for (int l = 0; l < 4; l++) {
        int K = cfgK[l], H = cfgH[l], C = cfgC[l], HC = H * C;
        int fusedN = 2 * HC;

        dim3 gg((fusedN + 127) / 128, (NN + 127) / 128);
        gemm_tf32<<<gg, 256>>>(x, inSel[l], Wl[l], Wr[l], NN, HC, fusedN, K);

        init_md_kernel<<<(NN * H + 255) / 256, 256>>>(NN * H);

        edge_logits_kernel<<<(ET * 32 + 255) / 256, 256>>>(ei, att[l], H, C);
        edge_exp_kernel<<<(ET * H + 255) / 256, 256>>>(ei, H);

        init_out_kernel<<<(NN * HC + 255) / 256, 256>>>(out, outSel[l], bias[l], HC);
        edge_scatter_kernel<<<(ET * 32 + 255) / 256, 256>>>(ei, out, outSel[l], H, C);
    }
}

// round 3
// speedup vs baseline: 2.7360x; 1.6760x over previous
#include <cuda_runtime.h>
#include <cstdint>

#define NN 50000
#define NE 400000
#define ET (NN + NE)
#define NEG_SLOPE 0.2f

// ---------------- scratch (device globals) -----------------------------------
__device__ float g_xl[NN * 256];
__device__ float g_xr[NN * 256];
__device__ float g_hA[NN * 256];
__device__ float g_hB[NN * 256];
__device__ int   g_cnt[NN];
__device__ int   g_ofs[NN];
__device__ int   g_fill[NN];
__device__ int   g_srcList[ET];
__device__ int   g_bsum[256];
__device__ int   g_boff[256];
__device__ int   g_is64;

// ---------------- helpers ----------------------------------------------------
__device__ __forceinline__ const float* selIn(const float* ext, int sel) {
    return sel == 1 ? g_hA : (sel == 2 ? g_hB : ext);
}
__device__ __forceinline__ float* selOut(float* ext, int sel) {
    return sel == 1 ? g_hA : (sel == 2 ? g_hB : ext);
}

__device__ __forceinline__ float f2tf32(float f) {
    unsigned u;
    asm("cvt.rna.tf32.f32 %0, %1;" : "=r"(u) : "f"(f));
    return __uint_as_float(u);
}

__global__ void detect64_kernel(const int* __restrict__ ei) {
    if (threadIdx.x == 0 && blockIdx.x == 0) {
        int all0 = 1;
        for (int i = 0; i < 64; i++)
            if (ei[2 * i + 1] != 0) all0 = 0;
        g_is64 = all0;
    }
}

__device__ __forceinline__ void load_edge(const void* ei, int e, int& s, int& d) {
    if (e >= NE) { s = d = e - NE; return; }   // self loops appended at the end
    if (g_is64) {
        const long long* p = (const long long*)ei;
        s = (int)p[e]; d = (int)p[NE + e];
    } else {
        const int* p = (const int*)ei;
        s = p[e]; d = p[NE + e];
    }
}

// ---------------- CSR build ---------------------------------------------------
__global__ void zero_cnt_kernel() {
    int i = blockIdx.x * blockDim.x + threadIdx.x;
    if (i < NN) g_cnt[i] = 0;
}

__global__ void count_kernel(const void* ei) {
    int e = blockIdx.x * blockDim.x + threadIdx.x;
    if (e >= ET) return;
    int s, d; load_edge(ei, e, s, d);
    (void)s;
    atomicAdd(&g_cnt[d], 1);
}

// block-exclusive scan of g_cnt -> g_ofs, block totals -> g_bsum
__global__ void scan1_kernel() {
    __shared__ int ws[8];
    int tid = threadIdx.x, lane = tid & 31, wid = tid >> 5;
    int i = blockIdx.x * 256 + tid;
    int v = (i < NN) ? g_cnt[i] : 0;
    int x = v;
#pragma unroll
    for (int o = 1; o < 32; o <<= 1) {
        int y = __shfl_up_sync(0xffffffffu, x, o);
        if (lane >= o) x += y;
    }
    if (lane == 31) ws[wid] = x;
    __syncthreads();
    if (tid == 0) {
        int run = 0;
        for (int j = 0; j < 8; j++) { int t = ws[j]; ws[j] = run; run += t; }
        g_bsum[blockIdx.x] = run;
    }
    __syncthreads();
    if (i < NN) g_ofs[i] = x - v + ws[wid];
}

// exclusive scan of block totals (single block)
__global__ void scan2_kernel(int nb) {
    __shared__ int ws[8];
    int tid = threadIdx.x, lane = tid & 31, wid = tid >> 5;
    int v = (tid < nb) ? g_bsum[tid] : 0;
    int x = v;
#pragma unroll
    for (int o = 1; o < 32; o <<= 1) {
        int y = __shfl_up_sync(0xffffffffu, x, o);
        if (lane >= o) x += y;
    }
    if (lane == 31) ws[wid] = x;
    __syncthreads();
    if (tid == 0) {
        int run = 0;
        for (int j = 0; j < 8; j++) { int t = ws[j]; ws[j] = run; run += t; }
    }
    __syncthreads();
    if (tid < nb) g_boff[tid] = x - v + ws[wid];
}

__global__ void scan3_kernel() {
    int i = blockIdx.x * 256 + threadIdx.x;
    if (i >= NN) return;
    int o = g_ofs[i] + g_boff[blockIdx.x];
    g_ofs[i] = o;
    g_fill[i] = o;
}

__global__ void fill_kernel(const void* ei) {
    int e = blockIdx.x * blockDim.x + threadIdx.x;
    if (e >= ET) return;
    int s, d; load_edge(ei, e, s, d);
    int pos = atomicAdd(&g_fill[d], 1);
    g_srcList[pos] = s;
}

// ---------------- tf32 tensor-core GEMM --------------------------------------
#define MMA_TF32(d, a, b)                                                      \
    asm volatile(                                                              \
        "mma.sync.aligned.m16n8k8.row.col.f32.tf32.tf32.f32 "                  \
        "{%0,%1,%2,%3}, {%4,%5,%6,%7}, {%8,%9}, {%0,%1,%2,%3};"                \
        : "+f"(d[0]), "+f"(d[1]), "+f"(d[2]), "+f"(d[3])                       \
        : "r"(a[0]), "r"(a[1]), "r"(a[2]), "r"(a[3]), "r"(b[0]), "r"(b[1]))

__global__ __launch_bounds__(256, 2) void gemm_tf32(
    const float* __restrict__ Aext, int asel,
    const float* __restrict__ Wl, const float* __restrict__ Wr,
    int M, int HC, int fusedN, int K)
{
    __shared__ float As[128][36];
    __shared__ float Bs[32][132];

    const float* A = selIn(Aext, asel);

    int tid = threadIdx.x;
    int lane = tid & 31, warp = tid >> 5;
    int wm = (warp & 1) * 64, wn = (warp >> 1) * 32;
    int rowBase = blockIdx.y * 128, colBase = blockIdx.x * 128;

    float acc[4][4][4];
#pragma unroll
    for (int i = 0; i < 4; i++)
#pragma unroll
        for (int j = 0; j < 4; j++)
#pragma unroll
            for (int q = 0; q < 4; q++) acc[i][j][q] = 0.f;

    int aRow = tid >> 1, aCol = (tid & 1) * 16;
    int bRow = tid >> 3, bCol = (tid & 7) * 4;

    for (int k0 = 0; k0 < K; k0 += 32) {
        {
            int gr = rowBase + aRow;
            const float* ap = A + (size_t)gr * K + k0 + aCol;
#pragma unroll
            for (int j = 0; j < 4; j++) {
                float4 v = make_float4(0.f, 0.f, 0.f, 0.f);
                if (gr < M) v = *(const float4*)(ap + j * 4);
                int kc = aCol + j * 4;
                As[aRow][kc + 0] = f2tf32(v.x);
                As[aRow][kc + 1] = f2tf32(v.y);
                As[aRow][kc + 2] = f2tf32(v.z);
                As[aRow][kc + 3] = f2tf32(v.w);
            }
        }
        {
            int gk = k0 + bRow;
#pragma unroll
            for (int i = 0; i < 4; i++) {
                int col = bCol + i * 32;
                int gc = colBase + col;
                float4 v = make_float4(0.f, 0.f, 0.f, 0.f);
                if (gc < fusedN) {
                    const float* bp = (gc < HC)
                        ? (Wl + (size_t)gk * HC + gc)
                        : (Wr + (size_t)gk * HC + (gc - HC));
                    v = *(const float4*)bp;
                }
                Bs[bRow][col + 0] = f2tf32(v.x);
                Bs[bRow][col + 1] = f2tf32(v.y);
                Bs[bRow][col + 2] = f2tf32(v.z);
                Bs[bRow][col + 3] = f2tf32(v.w);
            }
        }
        __syncthreads();

        int r = lane >> 2, c = lane & 3;
#pragma unroll
        for (int ks = 0; ks < 4; ks++) {
            int kk = ks * 8;
            unsigned a[4][4], b[4][2];
#pragma unroll
            for (int mi = 0; mi < 4; mi++) {
                int rb = wm + mi * 16 + r;
                a[mi][0] = __float_as_uint(As[rb][kk + c]);
                a[mi][1] = __float_as_uint(As[rb + 8][kk + c]);
                a[mi][2] = __float_as_uint(As[rb][kk + c + 4]);
                a[mi][3] = __float_as_uint(As[rb + 8][kk + c + 4]);
            }
#pragma unroll
            for (int ni = 0; ni < 4; ni++) {
                int nb = wn + ni * 8 + r;
                b[ni][0] = __float_as_uint(Bs[kk + c][nb]);
                b[ni][1] = __float_as_uint(Bs[kk + c + 4][nb]);
            }
#pragma unroll
            for (int mi = 0; mi < 4; mi++)
#pragma unroll
                for (int ni = 0; ni < 4; ni++)
                    MMA_TF32(acc[mi][ni], a[mi], b[ni]);
        }
        __syncthreads();
    }

    int r = lane >> 2, c = (lane & 3) * 2;
#pragma unroll
    for (int mi = 0; mi < 4; mi++) {
#pragma unroll
        for (int ni = 0; ni < 4; ni++) {
            int col = colBase + wn + ni * 8 + c;
            if (col >= fusedN) continue;
            float* base; int cc;
            if (col < HC) { base = g_xl; cc = col; }
            else          { base = g_xr; cc = col - HC; }
#pragma unroll
            for (int half = 0; half < 2; half++) {
                int row = rowBase + wm + mi * 16 + r + half * 8;
                if (row < M) {
                    *(float2*)(base + (size_t)row * HC + cc) =
                        make_float2(acc[mi][ni][half * 2],
                                    acc[mi][ni][half * 2 + 1]);
                }
            }
        }
    }
}

// ---------------- fused per-node aggregation (online softmax) ----------------
// One warp per dst node. V floats per lane per head (V*32 == C).
template <int H, int C>
__global__ __launch_bounds__(256) void gat_agg_kernel(
    const float* __restrict__ att, const float* __restrict__ bias,
    float* outext, int osel)
{
    constexpr int HC = H * C;
    constexpr int V = C / 32;   // 4 for C=128, 1 for C=32

    int nd = (blockIdx.x * blockDim.x + threadIdx.x) >> 5;
    int lane = threadIdx.x & 31;
    if (nd >= NN) return;

    float xr[H][V], at[H][V], acc[H][V];
    float m[H], den[H];

    const float* xrp = g_xr + (size_t)nd * HC;
#pragma unroll
    for (int h = 0; h < H; h++) {
        m[h] = -1e30f; den[h] = 0.f;
#pragma unroll
        for (int v = 0; v < V; v++) {
            int col = h * C + lane * V + v;
            xr[h][v] = xrp[col];
            at[h][v] = att[col];
            acc[h][v] = 0.f;
        }
    }

    int beg = g_ofs[nd];
    int end = (nd == NN - 1) ? ET : g_ofs[nd + 1];

    for (int i = beg; i < end; i++) {
        int s = g_srcList[i];
        const float* xlp = g_xl + (size_t)s * HC;

        float xv[H][V];
        float dot[H];
#pragma unroll
        for (int h = 0; h < H; h++) {
            if (V == 4) {
                float4 t = *(const float4*)(xlp + h * C + lane * 4);
                xv[h][0] = t.x; xv[h][1] = t.y; xv[h][2] = t.z; xv[h][3] = t.w;
            } else {
                xv[h][0] = xlp[h * C + lane];
            }
            float dd = 0.f;
#pragma unroll
            for (int v = 0; v < V; v++) {
                float e = xv[h][v] + xr[h][v];
                e = (e > 0.f) ? e : NEG_SLOPE * e;
                dd += e * at[h][v];
            }
            dot[h] = dd;
        }
#pragma unroll
        for (int o = 16; o; o >>= 1) {
#pragma unroll
            for (int h = 0; h < H; h++)
                dot[h] += __shfl_xor_sync(0xffffffffu, dot[h], o);
        }
#pragma unroll
        for (int h = 0; h < H; h++) {
            float logit = dot[h];
            float p;
            if (logit > m[h]) {
                float sc = __expf(m[h] - logit);
                den[h] *= sc;
#pragma unroll
                for (int v = 0; v < V; v++) acc[h][v] *= sc;
                m[h] = logit;
                p = 1.f;
            } else {
                p = __expf(logit - m[h]);
            }
            den[h] += p;
#pragma unroll
            for (int v = 0; v < V; v++) acc[h][v] += p * xv[h][v];
        }
    }

    float* outp = selOut(outext, osel) + (size_t)nd * HC;
#pragma unroll
    for (int h = 0; h < H; h++) {
        float inv = 1.f / den[h];
        if (V == 4) {
            int col = h * C + lane * 4;
            float4 o;
            o.x = acc[h][0] * inv + bias[col + 0];
            o.y = acc[h][1] * inv + bias[col + 1];
            o.z = acc[h][2] * inv + bias[col + 2];
            o.w = acc[h][3] * inv + bias[col + 3];
            *(float4*)(outp + col) = o;
        } else {
            int col = h * C + lane;
            outp[col] = acc[h][0] * inv + bias[col];
        }
    }
}

// ---------------- launch -----------------------------------------------------
extern "C" void kernel_launch(void* const* d_in, const int* in_sizes, int n_in,
                              void* d_out, int out_size)
{
    const float* x  = (const float*)d_in[0];
    const void*  ei = d_in[1];
    const float* Wl[4]   = {(const float*)d_in[2],  (const float*)d_in[6],
                            (const float*)d_in[10], (const float*)d_in[14]};
    const float* Wr[4]   = {(const float*)d_in[3],  (const float*)d_in[7],
                            (const float*)d_in[11], (const float*)d_in[15]};
    const float* att[4]  = {(const float*)d_in[4],  (const float*)d_in[8],
                            (const float*)d_in[12], (const float*)d_in[16]};
    const float* bias[4] = {(const float*)d_in[5],  (const float*)d_in[9],
                            (const float*)d_in[13], (const float*)d_in[17]};
    float* out = (float*)d_out;

    detect64_kernel<<<1, 32>>>((const int*)ei);

    // CSR build (edge_index constant across layers)
    int nb = (NN + 255) / 256;
    zero_cnt_kernel<<<nb, 256>>>();
    count_kernel<<<(ET + 255) / 256, 256>>>(ei);
    scan1_kernel<<<nb, 256>>>();
    scan2_kernel<<<1, 256>>>(nb);
    scan3_kernel<<<nb, 256>>>();
    fill_kernel<<<(ET + 255) / 256, 256>>>(ei);

    const int cfgK[4] = {1024, 256, 256, 256};
    const int inSel[4]  = {0, 1, 2, 1};
    const int outSel[4] = {1, 2, 1, 0};

    int aggBlocks = (NN * 32 + 255) / 256;

    for (int l = 0; l < 4; l++) {
        int K = cfgK[l];
        int HC = (l == 3) ? 32 : 256;
        int fusedN = 2 * HC;

        dim3 gg((fusedN + 127) / 128, (NN + 127) / 128);
        gemm_tf32<<<gg, 256>>>(x, inSel[l], Wl[l], Wr[l], NN, HC, fusedN, K);

        if (l == 3)
            gat_agg_kernel<1, 32><<<aggBlocks, 256>>>(att[l], bias[l], out, outSel[l]);
        else
            gat_agg_kernel<2, 128><<<aggBlocks, 256>>>(att[l], bias[l], out, outSel[l]);
    }
}

// round 4
// speedup vs baseline: 4.1881x; 1.5307x over previous
#include <cuda_runtime.h>
#include <cstdint>

#define NN 50000
#define NE 400000
#define ET (NN + NE)
#define NEG_SLOPE 0.2f

// ---------------- scratch (device globals) -----------------------------------
__device__ float g_xl[NN * 256];
__device__ float g_xr[NN * 256];
__device__ float g_hA[NN * 256];
__device__ float g_hB[NN * 256];
__device__ int   g_cnt[NN];
__device__ int   g_ofs[NN];
__device__ int   g_fill[NN];
__device__ int   g_srcList[ET];
__device__ int   g_bsum[256];
__device__ int   g_boff[256];
__device__ int   g_is64;

// ---------------- helpers ----------------------------------------------------
__device__ __forceinline__ const float* selIn(const float* ext, int sel) {
    return sel == 1 ? g_hA : (sel == 2 ? g_hB : ext);
}
__device__ __forceinline__ float* selOut(float* ext, int sel) {
    return sel == 1 ? g_hA : (sel == 2 ? g_hB : ext);
}

// f32 -> tf32 (rna) in register
__device__ __forceinline__ unsigned t32(float f) {
    unsigned u;
    asm("cvt.rna.tf32.f32 %0, %1;" : "=r"(u) : "f"(f));
    return u;
}

__device__ __forceinline__ void cpasync16(const void* smem_dst, const void* gsrc, int sz) {
    unsigned dst = (unsigned)__cvta_generic_to_shared(smem_dst);
    asm volatile("cp.async.cg.shared.global [%0], [%1], 16, %2;"
                 :: "r"(dst), "l"(gsrc), "r"(sz));
}
#define CP_COMMIT() asm volatile("cp.async.commit_group;")
#define CP_WAIT1()  asm volatile("cp.async.wait_group 1;")

__global__ void detect64_kernel(const int* __restrict__ ei) {
    if (threadIdx.x == 0 && blockIdx.x == 0) {
        int all0 = 1;
        for (int i = 0; i < 64; i++)
            if (ei[2 * i + 1] != 0) all0 = 0;
        g_is64 = all0;
    }
}

__device__ __forceinline__ void load_edge(const void* ei, int e, int& s, int& d) {
    if (e >= NE) { s = d = e - NE; return; }   // self loops appended at the end
    if (g_is64) {
        const long long* p = (const long long*)ei;
        s = (int)p[e]; d = (int)p[NE + e];
    } else {
        const int* p = (const int*)ei;
        s = p[e]; d = p[NE + e];
    }
}

// ---------------- CSR build ---------------------------------------------------
__global__ void zero_cnt_kernel() {
    int i = blockIdx.x * blockDim.x + threadIdx.x;
    if (i < NN) g_cnt[i] = 0;
}

__global__ void count_kernel(const void* ei) {
    int e = blockIdx.x * blockDim.x + threadIdx.x;
    if (e >= ET) return;
    int s, d; load_edge(ei, e, s, d);
    (void)s;
    atomicAdd(&g_cnt[d], 1);
}

__global__ void scan1_kernel() {
    __shared__ int ws[8];
    int tid = threadIdx.x, lane = tid & 31, wid = tid >> 5;
    int i = blockIdx.x * 256 + tid;
    int v = (i < NN) ? g_cnt[i] : 0;
    int x = v;
#pragma unroll
    for (int o = 1; o < 32; o <<= 1) {
        int y = __shfl_up_sync(0xffffffffu, x, o);
        if (lane >= o) x += y;
    }
    if (lane == 31) ws[wid] = x;
    __syncthreads();
    if (tid == 0) {
        int run = 0;
        for (int j = 0; j < 8; j++) { int t = ws[j]; ws[j] = run; run += t; }
        g_bsum[blockIdx.x] = run;
    }
    __syncthreads();
    if (i < NN) g_ofs[i] = x - v + ws[wid];
}

__global__ void scan2_kernel(int nb) {
    __shared__ int ws[8];
    int tid = threadIdx.x, lane = tid & 31, wid = tid >> 5;
    int v = (tid < nb) ? g_bsum[tid] : 0;
    int x = v;
#pragma unroll
    for (int o = 1; o < 32; o <<= 1) {
        int y = __shfl_up_sync(0xffffffffu, x, o);
        if (lane >= o) x += y;
    }
    if (lane == 31) ws[wid] = x;
    __syncthreads();
    if (tid == 0) {
        int run = 0;
        for (int j = 0; j < 8; j++) { int t = ws[j]; ws[j] = run; run += t; }
    }
    __syncthreads();
    if (tid < nb) g_boff[tid] = x - v + ws[wid];
}

__global__ void scan3_kernel() {
    int i = blockIdx.x * 256 + threadIdx.x;
    if (i >= NN) return;
    int o = g_ofs[i] + g_boff[blockIdx.x];
    g_ofs[i] = o;
    g_fill[i] = o;
}

__global__ void fill_kernel(const void* ei) {
    int e = blockIdx.x * blockDim.x + threadIdx.x;
    if (e >= ET) return;
    int s, d; load_edge(ei, e, s, d);
    int pos = atomicAdd(&g_fill[d], 1);
    g_srcList[pos] = s;
}

// ---------------- tf32 tensor-core GEMM, cp.async double-buffered ------------
// [xl | xr] = A[M,K] @ [Wl | Wr], block 128x128, K-step 16, 2 stages.
#define MMA_TF32(d, a, b)                                                      \
    asm volatile(                                                              \
        "mma.sync.aligned.m16n8k8.row.col.f32.tf32.tf32.f32 "                  \
        "{%0,%1,%2,%3}, {%4,%5,%6,%7}, {%8,%9}, {%0,%1,%2,%3};"                \
        : "+f"(d[0]), "+f"(d[1]), "+f"(d[2]), "+f"(d[3])                       \
        : "r"(a[0]), "r"(a[1]), "r"(a[2]), "r"(a[3]), "r"(b[0]), "r"(b[1]))

__global__ __launch_bounds__(256, 2) void gemm_tf32(
    const float* __restrict__ Aext, int asel,
    const float* __restrict__ Wl, const float* __restrict__ Wr,
    int M, int HC, int fusedN, int K)
{
    __shared__ float As[2][128][20];   // 128 rows x 16 k, stride 20 (conflict-free)
    __shared__ float Bs[2][16][132];   // 16 k x 128 cols, stride 132

    const float* A = selIn(Aext, asel);

    int tid = threadIdx.x;
    int lane = tid & 31, warp = tid >> 5;
    int wm = (warp & 1) * 64, wn = (warp >> 1) * 32;
    int rowBase = blockIdx.y * 128, colBase = blockIdx.x * 128;

    float acc[4][4][4];
#pragma unroll
    for (int i = 0; i < 4; i++)
#pragma unroll
        for (int j = 0; j < 4; j++)
#pragma unroll
            for (int q = 0; q < 4; q++) acc[i][j][q] = 0.f;

    // A: thread covers rows aRow0, aRow0+64 at cols [aCol, aCol+4)
    int aRow0 = tid >> 2, aCol = (tid & 3) * 4;
    // B: thread covers k-rows bRow0, bRow0+8 at cols [bCol, bCol+4)
    int bRow0 = tid >> 5, bCol = (tid & 31) * 4;

    // B column routing (constant across k)
    int gc = colBase + bCol;
    const float* bColBase_ptr;
    int bsz;
    if (gc >= fusedN) { bColBase_ptr = Wl; bsz = 0; }
    else if (gc < HC) { bColBase_ptr = Wl + gc; bsz = 16; }
    else              { bColBase_ptr = Wr + (gc - HC); bsz = 16; }

    int gr0 = rowBase + aRow0, gr1 = rowBase + aRow0 + 64;
    const float* aPtr0 = A + (size_t)min(gr0, M - 1) * K + aCol;
    const float* aPtr1 = A + (size_t)min(gr1, M - 1) * K + aCol;
    int asz0 = (gr0 < M) ? 16 : 0;
    int asz1 = (gr1 < M) ? 16 : 0;

    int nK = K >> 4;

#define ISSUE(kt, buf)                                                          \
    do {                                                                        \
        int k0_ = (kt) << 4;                                                    \
        cpasync16(&As[buf][aRow0][aCol],      aPtr0 + k0_, asz0);               \
        cpasync16(&As[buf][aRow0 + 64][aCol], aPtr1 + k0_, asz1);               \
        cpasync16(&Bs[buf][bRow0][bCol],                                        \
                  bColBase_ptr + (size_t)(k0_ + bRow0) * HC, bsz);              \
        cpasync16(&Bs[buf][bRow0 + 8][bCol],                                    \
                  bColBase_ptr + (size_t)(k0_ + bRow0 + 8) * HC, bsz);          \
    } while (0)

    ISSUE(0, 0);
    CP_COMMIT();

    int buf = 0;
    int r = lane >> 2, c = lane & 3;

    for (int kt = 0; kt < nK; kt++) {
        if (kt + 1 < nK) ISSUE(kt + 1, buf ^ 1);
        CP_COMMIT();
        CP_WAIT1();
        __syncthreads();

#pragma unroll
        for (int ks = 0; ks < 2; ks++) {
            int kk = ks * 8;
            unsigned a[4][4], b[4][2];
#pragma unroll
            for (int mi = 0; mi < 4; mi++) {
                int rb = wm + mi * 16 + r;
                a[mi][0] = t32(As[buf][rb][kk + c]);
                a[mi][1] = t32(As[buf][rb + 8][kk + c]);
                a[mi][2] = t32(As[buf][rb][kk + c + 4]);
                a[mi][3] = t32(As[buf][rb + 8][kk + c + 4]);
            }
#pragma unroll
            for (int ni = 0; ni < 4; ni++) {
                int nb = wn + ni * 8 + r;
                b[ni][0] = t32(Bs[buf][kk + c][nb]);
                b[ni][1] = t32(Bs[buf][kk + c + 4][nb]);
            }
#pragma unroll
            for (int mi = 0; mi < 4; mi++)
#pragma unroll
                for (int ni = 0; ni < 4; ni++)
                    MMA_TF32(acc[mi][ni], a[mi], b[ni]);
        }
        __syncthreads();   // protect buf^1 (being computed next? no: protect reuse of buf)
        buf ^= 1;
    }
#undef ISSUE

    // ---- epilogue: route columns to g_xl / g_xr
    int c2 = (lane & 3) * 2;
#pragma unroll
    for (int mi = 0; mi < 4; mi++) {
#pragma unroll
        for (int ni = 0; ni < 4; ni++) {
            int col = colBase + wn + ni * 8 + c2;
            if (col >= fusedN) continue;
            float* base; int cc;
            if (col < HC) { base = g_xl; cc = col; }
            else          { base = g_xr; cc = col - HC; }
#pragma unroll
            for (int half = 0; half < 2; half++) {
                int row = rowBase + wm + mi * 16 + r + half * 8;
                if (row < M) {
                    *(float2*)(base + (size_t)row * HC + cc) =
                        make_float2(acc[mi][ni][half * 2],
                                    acc[mi][ni][half * 2 + 1]);
                }
            }
        }
    }
}

// ---------------- fused per-node aggregation (online softmax, unroll 2) ------
template <int H, int C>
__global__ __launch_bounds__(256) void gat_agg_kernel(
    const float* __restrict__ att, const float* __restrict__ bias,
    float* outext, int osel)
{
    constexpr int HC = H * C;
    constexpr int V = C / 32;   // 4 for C=128, 1 for C=32

    int nd = (blockIdx.x * blockDim.x + threadIdx.x) >> 5;
    int lane = threadIdx.x & 31;
    if (nd >= NN) return;

    float xr[H][V], at[H][V], acc[H][V];
    float m[H], den[H];

    const float* xrp = g_xr + (size_t)nd * HC;
#pragma unroll
    for (int h = 0; h < H; h++) {
        m[h] = -1e30f; den[h] = 0.f;
#pragma unroll
        for (int v = 0; v < V; v++) {
            int col = h * C + lane * V + v;
            xr[h][v] = xrp[col];
            at[h][v] = att[col];
            acc[h][v] = 0.f;
        }
    }

    int beg = g_ofs[nd];
    int end = (nd == NN - 1) ? ET : g_ofs[nd + 1];
    int i = beg;
    int endPair = beg + ((end - beg) & ~1);

    for (; i < endPair; i += 2) {
        int s0 = g_srcList[i];
        int s1 = g_srcList[i + 1];
        const float* p0 = g_xl + (size_t)s0 * HC;
        const float* p1 = g_xl + (size_t)s1 * HC;

        float xv0[H][V], xv1[H][V];
        float d0[H], d1[H];
#pragma unroll
        for (int h = 0; h < H; h++) {
            if (V == 4) {
                float4 t0 = *(const float4*)(p0 + h * C + lane * 4);
                float4 t1 = *(const float4*)(p1 + h * C + lane * 4);
                xv0[h][0] = t0.x; xv0[h][1] = t0.y; xv0[h][2] = t0.z; xv0[h][3] = t0.w;
                xv1[h][0] = t1.x; xv1[h][1] = t1.y; xv1[h][2] = t1.z; xv1[h][3] = t1.w;
            } else {
                xv0[h][0] = p0[h * C + lane];
                xv1[h][0] = p1[h * C + lane];
            }
            float a0 = 0.f, a1 = 0.f;
#pragma unroll
            for (int v = 0; v < V; v++) {
                float e0 = xv0[h][v] + xr[h][v];
                float e1 = xv1[h][v] + xr[h][v];
                e0 = (e0 > 0.f) ? e0 : NEG_SLOPE * e0;
                e1 = (e1 > 0.f) ? e1 : NEG_SLOPE * e1;
                a0 += e0 * at[h][v];
                a1 += e1 * at[h][v];
            }
            d0[h] = a0; d1[h] = a1;
        }
#pragma unroll
        for (int o = 16; o; o >>= 1) {
#pragma unroll
            for (int h = 0; h < H; h++) {
                d0[h] += __shfl_xor_sync(0xffffffffu, d0[h], o);
                d1[h] += __shfl_xor_sync(0xffffffffu, d1[h], o);
            }
        }
#pragma unroll
        for (int h = 0; h < H; h++) {
            float l0 = d0[h], l1 = d1[h];
            float mx = fmaxf(m[h], fmaxf(l0, l1));
            float sc = __expf(m[h] - mx);
            float q0 = __expf(l0 - mx);
            float q1 = __expf(l1 - mx);
            m[h] = mx;
            den[h] = den[h] * sc + q0 + q1;
#pragma unroll
            for (int v = 0; v < V; v++)
                acc[h][v] = acc[h][v] * sc + q0 * xv0[h][v] + q1 * xv1[h][v];
        }
    }

    if (i < end) {   // leftover single edge
        int s = g_srcList[i];
        const float* xlp = g_xl + (size_t)s * HC;
        float xv[H][V], dot[H];
#pragma unroll
        for (int h = 0; h < H; h++) {
            if (V == 4) {
                float4 t = *(const float4*)(xlp + h * C + lane * 4);
                xv[h][0] = t.x; xv[h][1] = t.y; xv[h][2] = t.z; xv[h][3] = t.w;
            } else {
                xv[h][0] = xlp[h * C + lane];
            }
            float dd = 0.f;
#pragma unroll
            for (int v = 0; v < V; v++) {
                float e = xv[h][v] + xr[h][v];
                e = (e > 0.f) ? e : NEG_SLOPE * e;
                dd += e * at[h][v];
            }
            dot[h] = dd;
        }
#pragma unroll
        for (int o = 16; o; o >>= 1)
#pragma unroll
            for (int h = 0; h < H; h++)
                dot[h] += __shfl_xor_sync(0xffffffffu, dot[h], o);
#pragma unroll
        for (int h = 0; h < H; h++) {
            float l = dot[h];
            float mx = fmaxf(m[h], l);
            float sc = __expf(m[h] - mx);
            float q = __expf(l - mx);
            m[h] = mx;
            den[h] = den[h] * sc + q;
#pragma unroll
            for (int v = 0; v < V; v++)
                acc[h][v] = acc[h][v] * sc + q * xv[h][v];
        }
    }

    float* outp = selOut(outext, osel) + (size_t)nd * HC;
#pragma unroll
    for (int h = 0; h < H; h++) {
        float inv = 1.f / den[h];
        if (V == 4) {
            int col = h * C + lane * 4;
            float4 o;
            o.x = acc[h][0] * inv + bias[col + 0];
            o.y = acc[h][1] * inv + bias[col + 1];
            o.z = acc[h][2] * inv + bias[col + 2];
            o.w = acc[h][3] * inv + bias[col + 3];
            *(float4*)(outp + col) = o;
        } else {
            int col = h * C + lane;
            outp[col] = acc[h][0] * inv + bias[col];
        }
    }
}

// ---------------- launch -----------------------------------------------------
extern "C" void kernel_launch(void* const* d_in, const int* in_sizes, int n_in,
                              void* d_out, int out_size)
{
    const float* x  = (const float*)d_in[0];
    const void*  ei = d_in[1];
    const float* Wl[4]   = {(const float*)d_in[2],  (const float*)d_in[6],
                            (const float*)d_in[10], (const float*)d_in[14]};
    const float* Wr[4]   = {(const float*)d_in[3],  (const float*)d_in[7],
                            (const float*)d_in[11], (const float*)d_in[15]};
    const float* att[4]  = {(const float*)d_in[4],  (const float*)d_in[8],
                            (const float*)d_in[12], (const float*)d_in[16]};
    const float* bias[4] = {(const float*)d_in[5],  (const float*)d_in[9],
                            (const float*)d_in[13], (const float*)d_in[17]};
    float* out = (float*)d_out;

    detect64_kernel<<<1, 32>>>((const int*)ei);

    // CSR build (edge_index constant across layers)
    int nb = (NN + 255) / 256;
    zero_cnt_kernel<<<nb, 256>>>();
    count_kernel<<<(ET + 255) / 256, 256>>>(ei);
    scan1_kernel<<<nb, 256>>>();
    scan2_kernel<<<1, 256>>>(nb);
    scan3_kernel<<<nb, 256>>>();
    fill_kernel<<<(ET + 255) / 256, 256>>>(ei);

    const int cfgK[4] = {1024, 256, 256, 256};
    const int inSel[4]  = {0, 1, 2, 1};
    const int outSel[4] = {1, 2, 1, 0};

    int aggBlocks = (NN * 32 + 255) / 256;

    for (int l = 0; l < 4; l++) {
        int K = cfgK[l];
        int HC = (l == 3) ? 32 : 256;
        int fusedN = 2 * HC;

        dim3 gg((fusedN + 127) / 128, (NN + 127) / 128);
        gemm_tf32<<<gg, 256>>>(x, inSel[l], Wl[l], Wr[l], NN, HC, fusedN, K);

        if (l == 3)
            gat_agg_kernel<1, 32><<<aggBlocks, 256>>>(att[l], bias[l], out, outSel[l]);
        else
            gat_agg_kernel<2, 128><<<aggBlocks, 256>>>(att[l], bias[l], out, outSel[l]);
    }
}